// round 9
// baseline (speedup 1.0000x reference)
#include <cuda_runtime.h>
#include <cuda_bf16.h>
#include <cstdint>

#define NROWS 262144
#define DD 128
#define HH 16
#define EE 21

#define THREADS 256
#define M_TILE 128                 // rows per slab (8 warps x 16 rows)
#define GRID_MAIN 148

#define XSLAB_BYTES (M_TILE * DD * 4)         // 65536
#define WSTRIDE 20                            // words per d-row: 16 W1 + 4 extras
#define WSLAB_BYTES (DD * WSTRIDE * 4)        // 10240
#define SMEM_BYTES (3 * XSLAB_BYTES + 3 * WSLAB_BYTES + 3 * M_TILE * 4)  // 228864

__device__ int g_counts[EE];
__device__ int g_cursor[EE];
__device__ int g_offsets[EE + 1];
__device__ int g_tileOff[EE + 1];
__device__ int g_numTiles;
__device__ int g_perm[NROWS];
__device__ float g_Wsplit[EE][DD * HH];   // tf32-rounded W1, [d][h] contiguous

// ---------------- K1: histogram (int4 vectorized) ----------------
__global__ void k_hist(const int* __restrict__ sid) {
    __shared__ int sh[EE];
    int tid = threadIdx.x;
    if (tid < EE) sh[tid] = 0;
    __syncthreads();
    int4 v = ((const int4*)sid)[blockIdx.x * blockDim.x + tid];
    atomicAdd(&sh[v.x], 1);
    atomicAdd(&sh[v.y], 1);
    atomicAdd(&sh[v.z], 1);
    atomicAdd(&sh[v.w], 1);
    __syncthreads();
    if (tid < EE) atomicAdd(&g_counts[tid], sh[tid]);
}

// ---------------- K2: block0 = warp scan; blocks 1..21 = tf32 weight prep ----
__global__ void k_scan_prep(const float* __restrict__ W1) {
    if (blockIdx.x == 0) {
        if (threadIdx.x < 32) {
            int t = threadIdx.x;
            int c  = (t < EE) ? g_counts[t] : 0;
            int tl = (c + M_TILE - 1) / M_TILE;
            int ic = c, it = tl;
            #pragma unroll
            for (int d = 1; d < 32; d <<= 1) {
                int vc = __shfl_up_sync(0xFFFFFFFFu, ic, d);
                int vt = __shfl_up_sync(0xFFFFFFFFu, it, d);
                if (t >= d) { ic += vc; it += vt; }
            }
            if (t < EE) {
                g_offsets[t] = ic - c;
                g_cursor[t]  = ic - c;
                g_tileOff[t] = it - tl;
                g_counts[t]  = 0;
            }
            int totC = __shfl_sync(0xFFFFFFFFu, ic, EE - 1);
            int totT = __shfl_sync(0xFFFFFFFFu, it, EE - 1);
            if (t == 0) {
                g_offsets[EE] = totC;
                g_tileOff[EE] = totT;
                g_numTiles = totT;
            }
        }
    } else {
        int e = blockIdx.x - 1;
        for (int i = threadIdx.x; i < DD * HH; i += blockDim.x) {
            float w = W1[e * DD * HH + i];
            uint32_t hb;
            asm("cvt.rna.tf32.f32 %0, %1;" : "=r"(hb) : "f"(w));
            g_Wsplit[e][i] = __uint_as_float(hb);
        }
    }
}

// ---------------- K3: scatter ----------------
__global__ void k_scatter(const int* __restrict__ sid) {
    __shared__ int sHist[EE];
    __shared__ int sBase[EE];
    int tid = threadIdx.x;
    if (tid < EE) sHist[tid] = 0;
    __syncthreads();
    int gid = blockIdx.x * blockDim.x + tid;
    int e = sid[gid];
    int myIdx = atomicAdd(&sHist[e], 1);
    __syncthreads();
    if (tid < EE) sBase[tid] = atomicAdd(&g_cursor[tid], sHist[tid]);
    __syncthreads();
    g_perm[sBase[e] + myIdx] = gid;
}

// ---------------- K4: tf32-MMA persistent expert MLP (W as A operand) -----
__device__ __forceinline__ void cp_async16(uint32_t dst, const void* src) {
    asm volatile("cp.async.cg.shared.global [%0], [%1], 16;\n" :: "r"(dst), "l"(src));
}
__device__ __forceinline__ void cp_async4(uint32_t dst, const void* src) {
    asm volatile("cp.async.ca.shared.global [%0], [%1], 4;\n" :: "r"(dst), "l"(src));
}
#define CP_COMMIT() asm volatile("cp.async.commit_group;" ::: "memory")
#define CP_WAIT2()  asm volatile("cp.async.wait_group 2;" ::: "memory")

#define MMA_TF32(C0,C1,C2,C3, A0,A1,A2,A3, B0,B1)                                  \
    asm volatile("mma.sync.aligned.m16n8k8.row.col.f32.tf32.tf32.f32 "             \
        "{%0,%1,%2,%3}, {%4,%5,%6,%7}, {%8,%9}, {%0,%1,%2,%3};"                    \
        : "+f"(C0), "+f"(C1), "+f"(C2), "+f"(C3)                                   \
        : "r"(A0), "r"(A1), "r"(A2), "r"(A3), "r"(B0), "r"(B1))

__global__ __launch_bounds__(THREADS, 1)
void k_main(const float* __restrict__ x,
            const float* __restrict__ W1,
            const float* __restrict__ b1,
            const float* __restrict__ W2,
            const float* __restrict__ b2,
            float* __restrict__ out)
{
    extern __shared__ float smem[];
    float* xs = smem;                                    // 3 x 64KB slabs (swizzled)
    float* wb = xs + 3 * (XSLAB_BYTES / 4);              // 3 x [128 d][20]
    int* sRow = (int*)(wb + 3 * (WSLAB_BYTES / 4));      // 3 x 128

    int nT = g_numTiles;
    int q = (nT + GRID_MAIN - 1) / GRID_MAIN;
    int t0 = blockIdx.x * q;
    int t1 = t0 + q; if (t1 > nT) t1 = nT;
    int n = t1 - t0;
    if (n <= 0) return;

    int tid = threadIdx.x;
    int wid = tid >> 5;
    int t = tid & 31;
    uint32_t xs_sh = (uint32_t)__cvta_generic_to_shared(xs);
    uint32_t wb_sh = (uint32_t)__cvta_generic_to_shared(wb);

    auto tile_meta = [&](int tt, int& e, int& rs, int& v) {
        e = 0;
        #pragma unroll
        for (int j = 1; j < EE; j++)
            if (tt >= g_tileOff[j]) e = j;
        int ti = tt - g_tileOff[e];
        rs = g_offsets[e] + ti * M_TILE;
        v = g_offsets[e + 1] - rs;
        if (v > M_TILE) v = M_TILE;
    };
    auto stage_w = [&](int e, int slot) {
        uint32_t dst = wb_sh + (uint32_t)slot * WSLAB_BYTES;
        const float* Ws = g_Wsplit[e];
        #pragma unroll
        for (int m = 0; m < 2; m++) {
            int idx = tid + m * THREADS;
            int d = idx >> 2, s = idx & 3;
            cp_async16(dst + (uint32_t)(d * 80 + s * 16), Ws + d * 16 + s * 4);
        }
        if (tid < 4)       cp_async16(dst + (uint32_t)(tid * 80 + 64), b1 + e * HH + tid * 4);
        else if (tid < 8)  cp_async16(dst + (uint32_t)(tid * 80 + 64), W2 + e * HH + (tid - 4) * 4);
        else if (tid == 8) cp_async4(dst + (uint32_t)(8 * 80 + 64), b2 + e);
    };
    auto stage_x = [&](int slot, const int* rp) {
        uint32_t bb = xs_sh + (uint32_t)slot * XSLAB_BYTES;
        #pragma unroll
        for (int m = 0; m < 16; m++) {
            int idx = tid + m * THREADS;       // 4096 16B chunks
            int r = idx >> 5, s = idx & 31;
            int row = rp[r];
            uint32_t dst = bb + (uint32_t)(r * 512) + (uint32_t)(((s ^ (r & 7)) << 4));
            cp_async16(dst, x + (size_t)row * DD + s * 4);
        }
    };

    // ---- prologue: slabs 0 and 1 ----
    int eSlot0 = -1, eSlot1 = -1, eSlot2 = -1;
    {
        int e0, rs0, v0;
        tile_meta(t0, e0, rs0, v0);
        if (tid < M_TILE) sRow[tid] = g_perm[rs0 + ((tid < v0) ? tid : 0)];
        int e1 = -1;
        if (n > 1) {
            int rs1, v1;
            tile_meta(t0 + 1, e1, rs1, v1);
            if (tid < M_TILE) sRow[M_TILE + tid] = g_perm[rs1 + ((tid < v1) ? tid : 0)];
        }
        __syncthreads();
        stage_w(e0, 0); eSlot0 = e0;
        stage_x(0, sRow);
        CP_COMMIT();
        if (n > 1) {
            stage_w(e1, 1); eSlot1 = e1;
            stage_x(1, sRow + M_TILE);
        }
        CP_COMMIT();
    }

    // prefetch perm rows for slab 2
    int rr = 0;
    if (n > 2) {
        int e2, rs2, v2;
        tile_meta(t0 + 2, e2, rs2, v2);
        if (tid < M_TILE) rr = g_perm[rs2 + ((tid < v2) ? tid : 0)];
    }

    // constant per-thread addressing
    // B (x) loads: row rw = wid*16 + g*8 + t/4 ; word = d ^ ((rw&7)<<2), rw&7 = t/4
    uint32_t xsw = (uint32_t)((t >> 2) << 2);           // word-level xor
    uint32_t xrow0 = (uint32_t)((wid * 16 + (t >> 2)) * 512);
    // A (W) frag smem base: word (8k + t%4)*20 + t/4
    uint32_t wa_lane = (uint32_t)(((t & 3) * WSTRIDE + (t >> 2)) * 4);

    // register-resident W A-fragments (tf32 bit patterns)
    uint32_t aw0[16], aw1[16], aw2[16], aw3[16];
    int eReg = -1;

    for (int j = 0; j < n; j++) {
        int slot  = j % 3;
        int slot2 = (j + 2) % 3;

        __syncthreads();                              // prior compute done; slot2 free
        if (j + 2 < n && tid < M_TILE) sRow[slot2 * M_TILE + tid] = rr;
        __syncthreads();

        if (j + 2 < n) {
            int e2, rs2, v2;
            tile_meta(t0 + j + 2, e2, rs2, v2);
            int eCur = (slot2 == 0) ? eSlot0 : (slot2 == 1) ? eSlot1 : eSlot2;
            if (e2 != eCur) {
                stage_w(e2, slot2);
                if (slot2 == 0) eSlot0 = e2; else if (slot2 == 1) eSlot1 = e2; else eSlot2 = e2;
            }
            stage_x(slot2, sRow + slot2 * M_TILE);
        }
        CP_COMMIT();

        // prefetch perm rows for slab j+3 (overlaps the wait)
        if (j + 3 < n) {
            int e3, rs3, v3;
            tile_meta(t0 + j + 3, e3, rs3, v3);
            if (tid < M_TILE) rr = g_perm[rs3 + ((tid < v3) ? tid : 0)];
        }

        int ej, rsj, vj;
        tile_meta(t0 + j, ej, rsj, vj);

        CP_WAIT2();
        __syncthreads();

        // reload W A-frags on expert change (rare)
        if (ej != eReg) {
            eReg = ej;
            uint32_t wsb = wb_sh + (uint32_t)slot * WSLAB_BYTES + wa_lane;
            #pragma unroll
            for (int k = 0; k < 16; k++) {
                uint32_t base = wsb + (uint32_t)(k * 8 * WSTRIDE * 4);
                asm("ld.shared.b32 %0, [%1];" : "=r"(aw0[k]) : "r"(base));         // h, d
                asm("ld.shared.b32 %0, [%1];" : "=r"(aw1[k]) : "r"(base + 32));    // h+8
                asm("ld.shared.b32 %0, [%1];" : "=r"(aw2[k]) : "r"(base + 320));   // d+4
                asm("ld.shared.b32 %0, [%1];" : "=r"(aw3[k]) : "r"(base + 352));   // h+8,d+4
            }
        }

        // ---- compute slab j: C[16 h][rows], x as B operand, hi+lo chains ----
        uint32_t xb = xs_sh + (uint32_t)slot * XSLAB_BYTES + xrow0;
        float g0h0 = 0.f, g0h1 = 0.f, g0h2 = 0.f, g0h3 = 0.f;   // group0 hi
        float g0l0 = 0.f, g0l1 = 0.f, g0l2 = 0.f, g0l3 = 0.f;   // group0 lo
        float g1h0 = 0.f, g1h1 = 0.f, g1h2 = 0.f, g1h3 = 0.f;   // group1 hi
        float g1l0 = 0.f, g1l1 = 0.f, g1l2 = 0.f, g1l3 = 0.f;   // group1 lo

        #pragma unroll
        for (int k = 0; k < 16; k++) {
            uint32_t w0 = ((uint32_t)(8 * k + (t & 3)) ^ xsw) << 2;
            uint32_t a00 = xb + w0;              // group0, d
            uint32_t a10 = a00 + 4096;           // group1 (+8 rows)
            float f00, f01, f10, f11;
            asm("ld.shared.f32 %0, [%1];" : "=f"(f00) : "r"(a00));
            asm("ld.shared.f32 %0, [%1];" : "=f"(f01) : "r"(a00 ^ 16u));
            asm("ld.shared.f32 %0, [%1];" : "=f"(f10) : "r"(a10));
            asm("ld.shared.f32 %0, [%1];" : "=f"(f11) : "r"(a10 ^ 16u));
            uint32_t h00, h01, h10, h11;
            asm("cvt.rna.tf32.f32 %0, %1;" : "=r"(h00) : "f"(f00));
            asm("cvt.rna.tf32.f32 %0, %1;" : "=r"(h01) : "f"(f01));
            asm("cvt.rna.tf32.f32 %0, %1;" : "=r"(h10) : "f"(f10));
            asm("cvt.rna.tf32.f32 %0, %1;" : "=r"(h11) : "f"(f11));
            uint32_t l00 = __float_as_uint(f00 - __uint_as_float(h00));
            uint32_t l01 = __float_as_uint(f01 - __uint_as_float(h01));
            uint32_t l10 = __float_as_uint(f10 - __uint_as_float(h10));
            uint32_t l11 = __float_as_uint(f11 - __uint_as_float(h11));

            MMA_TF32(g0h0, g0h1, g0h2, g0h3, aw0[k], aw1[k], aw2[k], aw3[k], h00, h01);
            MMA_TF32(g0l0, g0l1, g0l2, g0l3, aw0[k], aw1[k], aw2[k], aw3[k], l00, l01);
            MMA_TF32(g1h0, g1h1, g1h2, g1h3, aw0[k], aw1[k], aw2[k], aw3[k], h10, h11);
            MMA_TF32(g1l0, g1l1, g1l2, g1l3, aw0[k], aw1[k], aw2[k], aw3[k], l10, l11);
        }

        // ---- epilogue ----
        {
            uint32_t wxb = wb_sh + (uint32_t)slot * WSLAB_BYTES;
            int h = t >> 2;                       // this lane's h (and h+8)
            float b1lo, b1hi, w2lo, w2hi, b2v;
            asm("ld.shared.f32 %0, [%1];" : "=f"(b1lo)
                : "r"(wxb + (uint32_t)(((h >> 2) * WSTRIDE + 16 + (h & 3)) * 4)));
            asm("ld.shared.f32 %0, [%1];" : "=f"(b1hi)
                : "r"(wxb + (uint32_t)((((h + 8) >> 2) * WSTRIDE + 16 + (h & 3)) * 4)));
            asm("ld.shared.f32 %0, [%1];" : "=f"(w2lo)
                : "r"(wxb + (uint32_t)(((4 + (h >> 2)) * WSTRIDE + 16 + (h & 3)) * 4)));
            asm("ld.shared.f32 %0, [%1];" : "=f"(w2hi)
                : "r"(wxb + (uint32_t)(((4 + ((h + 8) >> 2)) * WSTRIDE + 16 + (h & 3)) * 4)));
            asm("ld.shared.f32 %0, [%1];" : "=f"(b2v)
                : "r"(wxb + (uint32_t)((8 * WSTRIDE + 16) * 4)));

            // group0: rows wid*16 + 2*(t&3) + {0,1}; group1: +8
            float p0e = fmaxf(g0h0 + g0l0 + b1lo, 0.f) * w2lo
                      + fmaxf(g0h2 + g0l2 + b1hi, 0.f) * w2hi;
            float p0o = fmaxf(g0h1 + g0l1 + b1lo, 0.f) * w2lo
                      + fmaxf(g0h3 + g0l3 + b1hi, 0.f) * w2hi;
            float p1e = fmaxf(g1h0 + g1l0 + b1lo, 0.f) * w2lo
                      + fmaxf(g1h2 + g1l2 + b1hi, 0.f) * w2hi;
            float p1o = fmaxf(g1h1 + g1l1 + b1lo, 0.f) * w2lo
                      + fmaxf(g1h3 + g1l3 + b1hi, 0.f) * w2hi;
            #pragma unroll
            for (int d = 4; d < 32; d <<= 1) {
                p0e += __shfl_xor_sync(0xFFFFFFFFu, p0e, d);
                p0o += __shfl_xor_sync(0xFFFFFFFFu, p0o, d);
                p1e += __shfl_xor_sync(0xFFFFFFFFu, p1e, d);
                p1o += __shfl_xor_sync(0xFFFFFFFFu, p1o, d);
            }
            if (t < 4) {
                const int* rp = sRow + slot * M_TILE;
                int r0 = wid * 16 + 2 * t;
                if (r0 < vj)      out[rp[r0]]     = fmaxf(p0e + b2v, 0.f);
                if (r0 + 1 < vj)  out[rp[r0 + 1]] = fmaxf(p0o + b2v, 0.f);
                int r1 = r0 + 8;
                if (r1 < vj)      out[rp[r1]]     = fmaxf(p1e + b2v, 0.f);
                if (r1 + 1 < vj)  out[rp[r1 + 1]] = fmaxf(p1o + b2v, 0.f);
            }
        }
    }
}

extern "C" void kernel_launch(void* const* d_in, const int* in_sizes, int n_in,
                              void* d_out, int out_size)
{
    const float* x   = (const float*)d_in[0];
    const int*   sid = (const int*)d_in[1];
    const float* W1  = (const float*)d_in[2];
    const float* b1  = (const float*)d_in[3];
    const float* W2  = (const float*)d_in[4];
    const float* b2  = (const float*)d_in[5];
    float* out = (float*)d_out;

    static bool attr_set = false;
    if (!attr_set) {
        cudaFuncSetAttribute(k_main, cudaFuncAttributeMaxDynamicSharedMemorySize, SMEM_BYTES);
        attr_set = true;
    }

    k_hist<<<NROWS / 4096, 1024>>>(sid);
    k_scan_prep<<<1 + EE, 128>>>(W1);
    k_scatter<<<NROWS / 1024, 1024>>>(sid);
    k_main<<<GRID_MAIN, THREADS, SMEM_BYTES>>>(x, W1, b1, W2, b2, out);
}